// round 16
// baseline (speedup 1.0000x reference)
#include <cuda_runtime.h>
#include <cuda_fp16.h>
#include <math.h>

#define BB 64
#define FF 128
#define TT 1024
#define HH 512
#define GG 2048
#define NBLK 128

typedef unsigned long long ull;
typedef unsigned int u32;

// ---------------- device globals (no allocation allowed) ----------------
__device__ __half  g_xh  [(size_t)TT * BB * FF];   // (T*B, F) f16
__device__ float   g_xg  [(size_t)TT * BB * GG];   // layer0 gate preacts (float4-cell layout)
__device__ __half  g_h016[(size_t)TT * BB * HH];   // layer0 h f16 [t][m][k]
__device__ __half  g_h116[(size_t)TT * BB * HH];   // layer1 h f16 [s][m][k]
__device__ u32     g_cnt;                          // barrier counter

// ---------------- helpers ----------------
__device__ __forceinline__ float sigf(float x) { return 1.f / (1.f + __expf(-x)); }

__device__ __forceinline__ void red_release_add(u32* p, u32 v) {
    asm volatile("red.release.gpu.global.add.u32 [%0], %1;" :: "l"(p), "r"(v) : "memory");
}
__device__ __forceinline__ u32 ld_acquire(const u32* p) {
    u32 v;
    asm volatile("ld.acquire.gpu.global.u32 %0, [%1];" : "=r"(v) : "l"(p) : "memory");
    return v;
}
__device__ __forceinline__ u32 smem_u32(const void* p) {
    u32 a;
    asm("{ .reg .u64 t; cvta.to.shared.u64 t, %1; cvt.u32.u64 %0, t; }" : "=r"(a) : "l"(p));
    return a;
}
__device__ __forceinline__ void cp_async16(u32 saddr, const void* gptr) {
    asm volatile("cp.async.cg.shared.global [%0], [%1], 16;" :: "r"(saddr), "l"(gptr) : "memory");
}
__device__ __forceinline__ void cp_commit() {
    asm volatile("cp.async.commit_group;" ::: "memory");
}
__device__ __forceinline__ void cp_wait1() {
    asm volatile("cp.async.wait_group 1;" ::: "memory");
}
__device__ __forceinline__ void cp_wait0() {
    asm volatile("cp.async.wait_group 0;" ::: "memory");
}
__device__ __forceinline__ void ldsm_x4(u32& r0, u32& r1, u32& r2, u32& r3, u32 addr) {
    asm volatile("ldmatrix.sync.aligned.m8n8.x4.shared.b16 {%0,%1,%2,%3}, [%4];"
                 : "=r"(r0), "=r"(r1), "=r"(r2), "=r"(r3) : "r"(addr));
}
__device__ __forceinline__ void mma16816(float& c0, float& c1, float& c2, float& c3,
                                         u32 a0, u32 a1, u32 a2, u32 a3, u32 b0, u32 b1) {
    asm volatile("mma.sync.aligned.m16n8k16.row.col.f32.f16.f16.f32 "
                 "{%0,%1,%2,%3}, {%4,%5,%6,%7}, {%8,%9}, {%0,%1,%2,%3};"
                 : "+f"(c0), "+f"(c1), "+f"(c2), "+f"(c3)
                 : "r"(a0), "r"(a1), "r"(a2), "r"(a3), "r"(b0), "r"(b1));
}

// ---------------- reset counter ----------------
__global__ void reset_kernel() {
    if (threadIdx.x == 0) g_cnt = 0u;
}

// ---------------- transpose x (B,F,T) f32 -> (T*B, F) f16 ----------------
__global__ void transpose_x_kernel(const float* __restrict__ x) {
    __shared__ float tile[32][33];
    int b  = blockIdx.z;
    int t0 = blockIdx.x * 32;
    int f0 = blockIdx.y * 32;
    for (int i = threadIdx.y; i < 32; i += 8)
        tile[i][threadIdx.x] = x[(size_t)b * FF * TT + (size_t)(f0 + i) * TT + t0 + threadIdx.x];
    __syncthreads();
    for (int i = threadIdx.y; i < 32; i += 8)
        g_xh[((size_t)(t0 + i) * BB + b) * FF + f0 + threadIdx.x] =
            __float2half(tile[threadIdx.x][i]);
}

// ---------------- layer0 input GEMM (HMMA): xg = xh(M,128) @ Wih0^T + b ----------------
// Output layout: gate n = q*512+hc -> C[row][(hc>>2)*16 + (hc&3)*4 + q]  (cell float4)
#define GA_OFF 0
#define GB_OFF 32768
#define GSM_TOTAL (32768 + 16384)
__global__ __launch_bounds__(256, 3)
void gemm_gates_hmma(const __half* __restrict__ Ah, const float* __restrict__ W,
                     const float* __restrict__ bih, const float* __restrict__ bhh,
                     float* __restrict__ C) {
    extern __shared__ __align__(16) char gsm[];
    const u32 asm_base = smem_u32(gsm + GA_OFF);
    const u32 bsm_base = smem_u32(gsm + GB_OFF);
    const int tid = threadIdx.x;
    const int wid = tid >> 5, lane = tid & 31;
    const int n0 = blockIdx.x * 64;
    const int m0 = blockIdx.y * 128;

    #pragma unroll
    for (int i = 0; i < 8; ++i) {
        int e = i * 256 + tid;
        int row = e >> 4, ch = e & 15;
        uint4 v = *(const uint4*)(Ah + ((size_t)(m0 + row)) * FF + ch * 8);
        *(uint4*)(gsm + GA_OFF + row * 256 + ((u32)(ch ^ (row & 7))) * 16) = v;
    }
    #pragma unroll
    for (int i = 0; i < 4; ++i) {
        int e = i * 256 + tid;
        int row = e >> 4, ch = e & 15;
        const float* wsrc = W + (size_t)(n0 + row) * FF + ch * 8;
        float4 f0 = *(const float4*)wsrc;
        float4 f1 = *(const float4*)(wsrc + 4);
        __half2 h0 = __floats2half2_rn(f0.x, f0.y), h1 = __floats2half2_rn(f0.z, f0.w);
        __half2 h2 = __floats2half2_rn(f1.x, f1.y), h3 = __floats2half2_rn(f1.z, f1.w);
        *(uint4*)(gsm + GB_OFF + row * 256 + ((u32)(ch ^ (row & 7))) * 16) =
            make_uint4(*(u32*)&h0, *(u32*)&h1, *(u32*)&h2, *(u32*)&h3);
    }
    __syncthreads();

    const int mt = wid;
    const int arow = mt * 16 + ((lane >> 3) & 1) * 8 + (lane & 7);
    const int at16 = (lane >> 4) & 1;
    const int as   = arow & 7;
    const u32 a_lane = asm_base + arow * 256;

    const int al = lane & 15;
    const int brow_l = al & 7;
    const int btsel = (al >> 3) & 1;

    float acc[8][4];
    #pragma unroll
    for (int nt = 0; nt < 8; ++nt)
        #pragma unroll
        for (int p = 0; p < 4; ++p) acc[nt][p] = 0.f;

    #pragma unroll
    for (int kt = 0; kt < 8; ++kt) {
        u32 ch = (u32)((2 * kt + at16) ^ as);
        u32 a0, a1, a2, a3;
        ldsm_x4(a0, a1, a2, a3, a_lane + ch * 16);
        #pragma unroll
        for (int nt = 0; nt < 8; ++nt) {
            int brow = nt * 8 + brow_l;
            u32 bch = (u32)((2 * kt + btsel) ^ (brow & 7));
            u32 b0, b1;
            asm volatile("ldmatrix.sync.aligned.m8n8.x2.shared.b16 {%0,%1}, [%2];"
                         : "=r"(b0), "=r"(b1) : "r"(bsm_base + brow * 256 + bch * 16));
            mma16816(acc[nt][0], acc[nt][1], acc[nt][2], acc[nt][3], a0, a1, a2, a3, b0, b1);
        }
    }

    const int crow = mt * 16 + (lane >> 2);
    #pragma unroll
    for (int nt = 0; nt < 8; ++nt) {
        int na = n0 + nt * 8 + 2 * (lane & 3);       // gates na, na+1 (same q, hc even)
        int q = na >> 9, hc = na & 511;
        size_t cb = (size_t)((hc >> 2) << 4) + (hc & 3) * 4 + q;
        float ba = bih[na] + bhh[na];
        float bb = bih[na + 1] + bhh[na + 1];
        size_t r0 = (size_t)(m0 + crow) * GG + cb;
        size_t r1 = (size_t)(m0 + crow + 8) * GG + cb;
        C[r0]     = acc[nt][0] + ba;
        C[r0 + 4] = acc[nt][1] + bb;
        C[r1]     = acc[nt][2] + ba;
        C[r1 + 4] = acc[nt][3] + bb;
    }
}

// ---------------- fused 2-layer persistent HMMA LSTM (lag-2 skew, pinned B) ----------------
// 256 threads / 8 warps, warp = (mt 0..3, kh2 0..1): m16 x n16 x half-K.
// B0 (Whh0), B1A (Whh1) pinned in registers; B1B (Wih1) in SMEM for the shadow pass.
// Shadow pass writes partials to gates1b (SMEM); cells sum body + shadow buffers.
// Split cp.async groups: layer0 body overlaps Hs1 transfer.
#define HS0_OFF  0
#define HS1_OFF  65536
#define B1B_OFF  131072
#define GT0_OFF  (131072 + 16384)              // [2][64][20] f32 = 10240B
#define GT1A_OFF (GT0_OFF + 10240)
#define GT1B_OFF (GT1A_OFF + 10240)
#define SMEM_TOTAL (GT1B_OFF + 10240)

__global__ __launch_bounds__(256, 1)
void lstm_fused(const float* __restrict__ xg,
                const float* __restrict__ Whh0,
                const float* __restrict__ Whh1, const float* __restrict__ Wih1,
                const float* __restrict__ bih1, const float* __restrict__ bhh1,
                __half* __restrict__ h016, __half* __restrict__ h116,
                float* __restrict__ finalout, u32* __restrict__ cnt) {
    extern __shared__ __align__(16) char smraw[];
    const u32 hs0_base = smem_u32(smraw + HS0_OFF);
    const u32 hs1_base = smem_u32(smraw + HS1_OFF);
    const u32 b1b_base = smem_u32(smraw + B1B_OFF);
    float* gates0  = (float*)(smraw + GT0_OFF);     // [2][64][20]
    float* gates1a = (float*)(smraw + GT1A_OFF);    // [2][64][20]
    float* gates1b = (float*)(smraw + GT1B_OFF);    // [2][64][20]

    const int tid = threadIdx.x, blk = blockIdx.x;
    const int wid = tid >> 5, lane = tid & 31;
    const int mt = wid & 3, kh2 = wid >> 2;         // kh2 0..1 (K half)

    // ---- stage weight slices: Whh0 -> HS0, Whh1 -> HS0+16K (temps), Wih1 -> B1B ----
    for (int e = tid; e < 1024; e += 256) {
        int row = e >> 6, c = e & 63;
        size_t wr = (size_t)((row & 3) * HH + blk * 4 + (row >> 2)) * HH + c * 8;
        u32 off = row * 1024 + ((u32)(c ^ (row & 7))) * 16;
        {
            float4 f0 = *(const float4*)(Whh0 + wr);
            float4 f1 = *(const float4*)(Whh0 + wr + 4);
            __half2 h0 = __floats2half2_rn(f0.x, f0.y), h1 = __floats2half2_rn(f0.z, f0.w);
            __half2 h2 = __floats2half2_rn(f1.x, f1.y), h3 = __floats2half2_rn(f1.z, f1.w);
            *(uint4*)(smraw + off) = make_uint4(*(u32*)&h0, *(u32*)&h1, *(u32*)&h2, *(u32*)&h3);
        }
        {
            float4 f0 = *(const float4*)(Whh1 + wr);
            float4 f1 = *(const float4*)(Whh1 + wr + 4);
            __half2 h0 = __floats2half2_rn(f0.x, f0.y), h1 = __floats2half2_rn(f0.z, f0.w);
            __half2 h2 = __floats2half2_rn(f1.x, f1.y), h3 = __floats2half2_rn(f1.z, f1.w);
            *(uint4*)(smraw + 16384 + off) = make_uint4(*(u32*)&h0, *(u32*)&h1, *(u32*)&h2, *(u32*)&h3);
        }
        {
            float4 f0 = *(const float4*)(Wih1 + wr);
            float4 f1 = *(const float4*)(Wih1 + wr + 4);
            __half2 h0 = __floats2half2_rn(f0.x, f0.y), h1 = __floats2half2_rn(f0.z, f0.w);
            __half2 h2 = __floats2half2_rn(f1.x, f1.y), h3 = __floats2half2_rn(f1.z, f1.w);
            *(uint4*)(smraw + B1B_OFF + off) = make_uint4(*(u32*)&h0, *(u32*)&h1, *(u32*)&h2, *(u32*)&h3);
        }
    }
    __syncthreads();

    // B ldsm_x4 lane mapping: 4 matrices = (tile0,k0),(tile0,k1),(tile1,k0),(tile1,k1)
    const int bg   = lane >> 3;
    const int blr  = lane & 7;
    const int brow = ((bg >> 1) << 3) + blr;
    const int btsel = bg & 1;

    // ---- pin B0 (Whh0) and B1A (Whh1) fragments: 16 ktiles x 4 regs each ----
    u32 b0f[64], b1af[64];
    #pragma unroll
    for (int j = 0; j < 16; ++j) {
        int kt = kh2 * 16 + j;
        u32 bch = (u32)(((2 * kt + btsel) ^ blr)) * 16;
        ldsm_x4(b0f[4 * j], b0f[4 * j + 1], b0f[4 * j + 2], b0f[4 * j + 3],
                hs0_base + brow * 1024 + bch);
        ldsm_x4(b1af[4 * j], b1af[4 * j + 1], b1af[4 * j + 2], b1af[4 * j + 3],
                hs0_base + 16384 + brow * 1024 + bch);
    }
    __syncthreads();

    const u32 b1b_lane = b1b_base + brow * 1024;

    // A ldsm lane mapping
    const int arow = mt * 16 + ((lane >> 3) & 1) * 8 + (lane & 7);
    const int at16 = (lane >> 4) & 1;
    const int as   = arow & 7;
    const u32 a0_lane = hs0_base + arow * 1024;
    const u32 a1_lane = hs1_base + arow * 1024;

    // cell mapping (all 256 threads)
    const int cm = tid >> 2, cj = tid & 3;
    const int col = blk * 4 + cj;
    float creg0 = 0.f, creg1 = 0.f;
    float b1g0 = bih1[0 * HH + col] + bhh1[0 * HH + col];
    float b1g1 = bih1[1 * HH + col] + bhh1[1 * HH + col];
    float b1g2 = bih1[2 * HH + col] + bhh1[2 * HH + col];
    float b1g3 = bih1[3 * HH + col] + bhh1[3 * HH + col];

    // C fragment coords; partial buffers for this kh2 (pitch 20)
    const int crow = mt * 16 + (lane >> 2);
    const int cc   = 2 * (lane & 3);
    float* g0p  = gates0  + kh2 * (64 * 20);
    float* g1ap = gates1a + kh2 * (64 * 20);
    float* g1bp = gates1b + kh2 * (64 * 20);

    #pragma unroll 1
    for (int i = 0; i <= TT + 1; ++i) {
        // prefetch xg for layer0 cell (single float4)
        float4 xv = make_float4(0.f, 0.f, 0.f, 0.f);
        if (i < TT)
            xv = *(const float4*)(xg + ((size_t)i * BB + cm) * GG + blk * 16 + cj * 4);

        // ---- stage Hs0 (group A), Hs1 (group B) ----
        if (i == 0) {
            #pragma unroll
            for (int r = 0; r < 16; ++r) {
                int e = r * 256 + tid;
                int row = e >> 6, sc = e & 63;
                u32 off = row * 1024 + ((u32)(sc ^ (row & 7))) * 16;
                *(uint4*)(smraw + HS0_OFF + off) = make_uint4(0u, 0u, 0u, 0u);
            }
        } else if (i <= TT) {
            const __half* hp0 = h016 + (size_t)(i - 1) * BB * HH;
            #pragma unroll
            for (int r = 0; r < 16; ++r) {
                int e = r * 256 + tid;
                int row = e >> 6, sc = e & 63;
                u32 off = row * 1024 + ((u32)(sc ^ (row & 7))) * 16;
                cp_async16(hs0_base + off, hp0 + (size_t)row * HH + sc * 8);
            }
        }
        cp_commit();
        if (i == 2) {
            #pragma unroll
            for (int r = 0; r < 16; ++r) {
                int e = r * 256 + tid;
                int row = e >> 6, sc = e & 63;
                u32 off = row * 1024 + ((u32)(sc ^ (row & 7))) * 16;
                *(uint4*)(smraw + HS1_OFF + off) = make_uint4(0u, 0u, 0u, 0u);
            }
        } else if (i >= 3 && i <= TT + 1) {
            const __half* hp1 = h116 + (size_t)(i - 3) * BB * HH;
            #pragma unroll
            for (int r = 0; r < 16; ++r) {
                int e = r * 256 + tid;
                int row = e >> 6, sc = e & 63;
                u32 off = row * 1024 + ((u32)(sc ^ (row & 7))) * 16;
                cp_async16(hs1_base + off, hp1 + (size_t)row * HH + sc * 8);
            }
        }
        cp_commit();

        cp_wait1();            // Hs0 group complete (Hs1 may still be in flight)
        __syncthreads();

        // ---- layer0 body: c = Hs0 @ B0^T (pinned B) ----
        if (i < TT) {
            float c00 = 0.f, c01 = 0.f, c02 = 0.f, c03 = 0.f;
            float c10 = 0.f, c11 = 0.f, c12 = 0.f, c13 = 0.f;
            #pragma unroll
            for (int j = 0; j < 16; ++j) {
                int kt = kh2 * 16 + j;
                u32 ch = (u32)((2 * kt + at16) ^ as);
                u32 a0, a1, a2, a3;
                ldsm_x4(a0, a1, a2, a3, a0_lane + ch * 16);
                mma16816(c00, c01, c02, c03, a0, a1, a2, a3, b0f[4 * j], b0f[4 * j + 1]);
                mma16816(c10, c11, c12, c13, a0, a1, a2, a3, b0f[4 * j + 2], b0f[4 * j + 3]);
            }
            *(float2*)&g0p[crow * 20 + cc]           = make_float2(c00, c01);
            *(float2*)&g0p[(crow + 8) * 20 + cc]     = make_float2(c02, c03);
            *(float2*)&g0p[crow * 20 + 8 + cc]       = make_float2(c10, c11);
            *(float2*)&g0p[(crow + 8) * 20 + 8 + cc] = make_float2(c12, c13);
        }

        cp_wait0();            // Hs1 group complete
        __syncthreads();

        // ---- layer1 body: e = Hs1 @ B1A^T (pinned B) ----
        if (i >= 2) {
            float e00 = 0.f, e01 = 0.f, e02 = 0.f, e03 = 0.f;
            float e10 = 0.f, e11 = 0.f, e12 = 0.f, e13 = 0.f;
            #pragma unroll
            for (int j = 0; j < 16; ++j) {
                int kt = kh2 * 16 + j;
                u32 ch = (u32)((2 * kt + at16) ^ as);
                u32 a0, a1, a2, a3;
                ldsm_x4(a0, a1, a2, a3, a1_lane + ch * 16);
                mma16816(e00, e01, e02, e03, a0, a1, a2, a3, b1af[4 * j], b1af[4 * j + 1]);
                mma16816(e10, e11, e12, e13, a0, a1, a2, a3, b1af[4 * j + 2], b1af[4 * j + 3]);
            }
            *(float2*)&g1ap[crow * 20 + cc]           = make_float2(e00, e01);
            *(float2*)&g1ap[(crow + 8) * 20 + cc]     = make_float2(e02, e03);
            *(float2*)&g1ap[crow * 20 + 8 + cc]       = make_float2(e10, e11);
            *(float2*)&g1ap[(crow + 8) * 20 + 8 + cc] = make_float2(e12, e13);
        }
        __syncthreads();

        // ---- cells (all 256 threads) ----
        if (i < TT) {
            const float* gp = gates0 + cm * 20 + 4 * cj;
            float4 v0 = *(const float4*)(gp);
            float4 v1 = *(const float4*)(gp + 1280);
            float s0 = v0.x + v1.x, s1 = v0.y + v1.y;
            float s2 = v0.z + v1.z, s3 = v0.w + v1.w;
            float gi_ = sigf (s0 + xv.x);
            float gf_ = sigf (s1 + xv.y);
            float gz_ = tanhf(s2 + xv.z);
            float go_ = sigf (s3 + xv.w);
            creg0 = gf_ * creg0 + gi_ * gz_;
            float h = go_ * tanhf(creg0);
            h016[((size_t)i * BB + cm) * HH + col] = __float2half(h);
        }
        if (i >= 2) {
            const float* ga = gates1a + cm * 20 + 4 * cj;
            const float* gb = gates1b + cm * 20 + 4 * cj;
            float4 v0 = *(const float4*)(ga);
            float4 v1 = *(const float4*)(ga + 1280);
            float4 w0 = *(const float4*)(gb);
            float4 w1 = *(const float4*)(gb + 1280);
            float s0 = v0.x + v1.x + w0.x + w1.x;
            float s1 = v0.y + v1.y + w0.y + w1.y;
            float s2 = v0.z + v1.z + w0.z + w1.z;
            float s3 = v0.w + v1.w + w0.w + w1.w;
            float gi_ = sigf (s0 + b1g0);
            float gf_ = sigf (s1 + b1g1);
            float gz_ = tanhf(s2 + b1g2);
            float go_ = sigf (s3 + b1g3);
            creg1 = gf_ * creg1 + gi_ * gz_;
            float h = go_ * tanhf(creg1);
            h116[((size_t)(i - 2) * BB + cm) * HH + col] = __float2half(h);
            if (i == TT + 1) finalout[(size_t)cm * HH + col] = h;
        }

        // ---- tail: arrive early, B1B shadow pass -> gates1b, poll ----
        if (i <= TT) {
            __syncthreads();
            if (tid == 0) red_release_add(cnt, 1u);
            if (i >= 1) {
                float d00 = 0.f, d01 = 0.f, d02 = 0.f, d03 = 0.f;
                float d10 = 0.f, d11 = 0.f, d12 = 0.f, d13 = 0.f;
                #pragma unroll
                for (int j = 0; j < 16; ++j) {
                    int kt = kh2 * 16 + j;
                    u32 ch  = (u32)((2 * kt + at16) ^ as);
                    u32 bch = (u32)((2 * kt + btsel) ^ blr);
                    u32 a0, a1, a2, a3, p0, p1, p2, p3;
                    ldsm_x4(a0, a1, a2, a3, a0_lane + ch * 16);
                    ldsm_x4(p0, p1, p2, p3, b1b_lane + bch * 16);
                    mma16816(d00, d01, d02, d03, a0, a1, a2, a3, p0, p1);
                    mma16816(d10, d11, d12, d13, a0, a1, a2, a3, p2, p3);
                }
                *(float2*)&g1bp[crow * 20 + cc]           = make_float2(d00, d01);
                *(float2*)&g1bp[(crow + 8) * 20 + cc]     = make_float2(d02, d03);
                *(float2*)&g1bp[crow * 20 + 8 + cc]       = make_float2(d10, d11);
                *(float2*)&g1bp[(crow + 8) * 20 + 8 + cc] = make_float2(d12, d13);
            }
            if (tid == 0) {
                u32 target = (u32)NBLK * (u32)(i + 1);
                while (ld_acquire(cnt) < target) {}
            }
            __syncthreads();
        }
    }
}

// ---------------- launch ----------------
extern "C" void kernel_launch(void* const* d_in, const int* in_sizes, int n_in,
                              void* d_out, int out_size) {
    const float* x    = (const float*)d_in[0];
    const float* Wih0 = (const float*)d_in[1];
    const float* Whh0 = (const float*)d_in[2];
    const float* bih0 = (const float*)d_in[3];
    const float* bhh0 = (const float*)d_in[4];
    const float* Wih1 = (const float*)d_in[5];
    const float* Whh1 = (const float*)d_in[6];
    const float* bih1 = (const float*)d_in[7];
    const float* bhh1 = (const float*)d_in[8];
    float* out = (float*)d_out;

    float* xg;
    __half *xh, *h016, *h116;
    u32* cnt;
    cudaGetSymbolAddress((void**)&xh,   g_xh);
    cudaGetSymbolAddress((void**)&xg,   g_xg);
    cudaGetSymbolAddress((void**)&h016, g_h016);
    cudaGetSymbolAddress((void**)&h116, g_h116);
    cudaGetSymbolAddress((void**)&cnt,  g_cnt);

    cudaFuncSetAttribute(lstm_fused, cudaFuncAttributeMaxDynamicSharedMemorySize, SMEM_TOTAL);
    cudaFuncSetAttribute(gemm_gates_hmma, cudaFuncAttributeMaxDynamicSharedMemorySize, GSM_TOTAL);

    reset_kernel<<<1, 32>>>();

    dim3 tb(32, 8), tg(TT / 32, FF / 32, BB);
    transpose_x_kernel<<<tg, tb>>>(x);

    gemm_gates_hmma<<<dim3(GG / 64, TT * BB / 128), 256, GSM_TOTAL>>>(xh, Wih0, bih0, bhh0, xg);
    lstm_fused<<<NBLK, 256, SMEM_TOTAL>>>(xg, Whh0, Whh1, Wih1, bih1, bhh1,
                                          h016, h116, out, cnt);
}